// round 12
// baseline (speedup 1.0000x reference)
#include <cuda_runtime.h>

// Shapes (fixed by the reference setup_inputs):
//   predicted_noise [32, 4, 512, 512] f32   (d_in[0])
//   target_noise    [32, 4, 512, 512] f32   (d_in[1])
//   text_tokens     [32, 64] int64          (d_in[2], UNUSED by the math)
//   text_positions  [32, 64, 2] f32         (d_in[3])
// Output: 1 x f32 scalar.
//
// result = [ sum(d^2) + 3 * sum_{masked px} d^2 ] / N,  d = p - t
// (WEIGHT = 1.0; mask = union of 10x10 boxes around valid tokens.)
//
// R7 single fused kernel:
//   - CTAs 0..63 paint the 1MB mask bitfield (register-built rows, coalesced
//     overwrite, no zeroing), then raise g_paint_done. They are the lowest
//     block ids, so they are scheduled first -> anyone spinning on the flag
//     waits only on CTAs that are already running (deadlock-free).
//   - Phase A: ALL CTAs stream sum(d^2) with a mask-free minimal body
//     (2x LDG.128 + 8 FP ops). No dependency on paint.
//   - Phase B: after streaming (>> paint time, spin is instantaneous), each
//     of the first 262144 threads owns one mask word and gathers 3*d^2 over
//     its set bits (~6MB total).
//   - Last-block fold writes the scalar and resets the paint flag.

#define NB 32
#define NC 4
#define NH 512
#define NW 512
#define NT 64
#define BOX 5

#define WORDS_PER_ROW   (NW / 32)                 // 16
#define WORDS_PER_BATCH (NH * WORDS_PER_ROW)      // 8192 = 2^13
#define MASK_WORDS      (NB * WORDS_PER_BATCH)    // 262144 (1 MB)
#define N_ELEMS         (NB * NC * NH * NW)       // 33554432 = 2^25
#define N4              (N_ELEMS / 4)             // 8388608

#define RGRID    1184                              // 148 SMs * 8 CTAs
#define RTHREADS 256
#define PAINT_CTAS 64                              // 16384 rows / 256 thr

__device__ unsigned g_mask[MASK_WORDS];
__device__ float    g_partials[RGRID];
__device__ unsigned g_count = 0;        // wraps via atomicInc each replay
__device__ volatile unsigned g_paint_done = 0;  // reset by last block

__global__ void __launch_bounds__(RTHREADS)
fused_loss_kernel(const float4* __restrict__ p4,
                  const float4* __restrict__ q4,
                  const float*  __restrict__ pf,
                  const float*  __restrict__ qf,
                  const float*  __restrict__ pos,
                  float* __restrict__ out) {
    const int tid = threadIdx.x;
    const int bid = blockIdx.x;

    // ================= paint (CTAs 0..63 only) =================
    if (bid < PAINT_CTAS) {
        __shared__ float sx[NT], sy[NT];
        const int batch = bid >> 1;                    // 2 CTAs per batch
        const int row   = ((bid & 1) << 8) + tid;      // 0..511

        if (tid < NT * 2) {
            float v = pos[(batch * NT) * 2 + tid];
            if (tid & 1) sy[tid >> 1] = v; else sx[tid >> 1] = v;
        }
        __syncthreads();

        unsigned w[WORDS_PER_ROW];
        #pragma unroll
        for (int k = 0; k < WORDS_PER_ROW; k++) w[k] = 0u;

        for (int t = 0; t < NT; t++) {
            float x = sx[t], y = sy[t];
            if (!(x > 0.0f && y > 0.0f)) continue;
            int yp = (int)floorf(y * (float)NH);
            if (row < yp - BOX || row >= yp + BOX) continue;
            int xp = (int)floorf(x * (float)NW);
            int x0 = max(xp - BOX, 0);
            int x1 = min(xp + BOX, NW);
            if (x0 >= x1) continue;
            int w0 = x0 >> 5;
            int w1 = (x1 - 1) >> 5;
            if (w0 == w1) {
                w[w0] |= ((1u << (x1 - x0)) - 1u) << (x0 & 31);  // width<=10<32
            } else {
                w[w0] |= ~0u << (x0 & 31);
                w[w1] |= (1u << (x1 - (w1 << 5))) - 1u;          // 1..9 bits
            }
        }

        uint4* dst = (uint4*)&g_mask[batch * WORDS_PER_BATCH + row * WORDS_PER_ROW];
        #pragma unroll
        for (int k = 0; k < 4; k++)
            dst[k] = make_uint4(w[4 * k], w[4 * k + 1], w[4 * k + 2], w[4 * k + 3]);

        __syncthreads();
        if (tid == 0) {
            __threadfence();
            atomicAdd((unsigned*)&g_paint_done, 1u);
        }
    }

    // ================= Phase A: mask-free stream of sum(d^2) ===========
    float sum = 0.0f;
    {
        const int stride = RGRID * RTHREADS;
        #pragma unroll 4
        for (int i = bid * RTHREADS + tid; i < N4; i += stride) {
            float4 a = p4[i];
            float4 b = q4[i];
            float d0 = a.x - b.x;
            float d1 = a.y - b.y;
            float d2 = a.z - b.z;
            float d3 = a.w - b.w;
            sum = fmaf(d0, d0, sum);
            sum = fmaf(d1, d1, sum);
            sum = fmaf(d2, d2, sum);
            sum = fmaf(d3, d3, sum);
        }
    }

    // ================= wait for paint (free: stream >> paint) ==========
    while (g_paint_done != PAINT_CTAS) { }
    __threadfence();

    // ================= Phase B: masked fixup, one word per thread ======
    {
        const int g = bid * RTHREADS + tid;
        if (g < MASK_WORDS) {
            unsigned w = g_mask[g];
            if (w) {
                const int batch = g >> 13;
                const int rem   = g & 8191;
                const int row   = rem >> 4;
                const int cbase = (rem & 15) << 5;
                // float index of (batch, ch=0, row, col=0)
                const int base = (batch << 20) + (row << 9);
                float bsum = 0.0f;
                while (w) {
                    int bit = __ffs(w) - 1;
                    w &= w - 1;
                    int idx = base + cbase + bit;
                    #pragma unroll
                    for (int ch = 0; ch < NC; ch++) {
                        float d = pf[idx + (ch << 18)] - qf[idx + (ch << 18)];
                        bsum = fmaf(d, d, bsum);
                    }
                }
                sum = fmaf(3.0f, bsum, sum);
            }
        }
    }

    // ================= block reduce + last-block fold ==================
    #pragma unroll
    for (int o = 16; o > 0; o >>= 1)
        sum += __shfl_xor_sync(0xFFFFFFFFu, sum, o);
    __shared__ float ssum[RTHREADS / 32];
    __shared__ bool  s_last;
    int lane = tid & 31, wid = tid >> 5;
    if (lane == 0) ssum[wid] = sum;
    __syncthreads();
    if (wid == 0) {
        float v = (lane < RTHREADS / 32) ? ssum[lane] : 0.0f;
        #pragma unroll
        for (int o = 4; o > 0; o >>= 1)
            v += __shfl_xor_sync(0xFFFFFFFFu, v, o);
        if (lane == 0) {
            g_partials[bid] = v;
            __threadfence();
            unsigned prev = atomicInc(&g_count, RGRID - 1);  // wraps after last
            s_last = (prev == RGRID - 1);
        }
    }
    __syncthreads();

    if (s_last) {
        double d = 0.0;
        for (int i = tid; i < RGRID; i += RTHREADS)
            d += (double)g_partials[i];
        #pragma unroll
        for (int o = 16; o > 0; o >>= 1)
            d += __shfl_xor_sync(0xFFFFFFFFu, d, o);
        __shared__ double dsum[RTHREADS / 32];
        if (lane == 0) dsum[wid] = d;
        __syncthreads();
        if (wid == 0) {
            double t = (lane < RTHREADS / 32) ? dsum[lane] : 0.0;
            #pragma unroll
            for (int o = 4; o > 0; o >>= 1)
                t += __shfl_xor_sync(0xFFFFFFFFu, t, o);
            if (lane == 0) {
                out[0] = (float)(t * (1.0 / (double)N_ELEMS));
                g_paint_done = 0;          // reset for next graph replay
                __threadfence();
            }
        }
    }
}

extern "C" void kernel_launch(void* const* d_in, const int* in_sizes, int n_in,
                              void* d_out, int out_size) {
    const float* pred = (const float*)d_in[0];
    const float* targ = (const float*)d_in[1];
    // d_in[2] (text_tokens) is unused by the math.
    const float* pos  = (const float*)d_in[3];
    fused_loss_kernel<<<RGRID, RTHREADS>>>((const float4*)pred,
                                           (const float4*)targ,
                                           pred, targ, pos, (float*)d_out);
}

// round 13
// speedup vs baseline: 1.0640x; 1.0640x over previous
#include <cuda_runtime.h>

// Shapes (fixed by the reference setup_inputs):
//   predicted_noise [32, 4, 512, 512] f32   (d_in[0])
//   target_noise    [32, 4, 512, 512] f32   (d_in[1])
//   text_tokens     [32, 64] int64          (d_in[2], UNUSED by the math)
//   text_positions  [32, 64, 2] f32         (d_in[3])
// Output: 1 x f32 scalar.
//
// result = [ sum(d^2) + 3 * sum_{masked px} d^2 ] / N,  d = p - t
// (WEIGHT = 1.0; mask = union of 10x10 boxes around valid tokens.)
//
// R8 = R7 (fused paint + mask-free stream + sparse fixup) with the one fix
// that matters: __launch_bounds__(256, 8) forces <=32 regs/thread so the
// kernel keeps 8 CTAs/SM (R7 compiled to 33 regs -> 40-reg bucket -> 6
// CTAs/SM -> occ 69% -> regression). Spills, if any, land in the cold
// paint / final-fold paths only.

#define NB 32
#define NC 4
#define NH 512
#define NW 512
#define NT 64
#define BOX 5

#define WORDS_PER_ROW   (NW / 32)                 // 16
#define WORDS_PER_BATCH (NH * WORDS_PER_ROW)      // 8192 = 2^13
#define MASK_WORDS      (NB * WORDS_PER_BATCH)    // 262144 (1 MB)
#define N_ELEMS         (NB * NC * NH * NW)       // 33554432 = 2^25
#define N4              (N_ELEMS / 4)             // 8388608

#define RGRID    1184                              // 148 SMs * 8 CTAs: one full wave
#define RTHREADS 256
#define PAINT_CTAS 64                              // 16384 rows / 256 thr

__device__ unsigned g_mask[MASK_WORDS];
__device__ float    g_partials[RGRID];
__device__ unsigned g_count = 0;        // wraps via atomicInc each replay
__device__ volatile unsigned g_paint_done = 0;  // reset by last block

__global__ void __launch_bounds__(RTHREADS, 8)   // force <=32 regs: 8 CTAs/SM
fused_loss_kernel(const float4* __restrict__ p4,
                  const float4* __restrict__ q4,
                  const float*  __restrict__ pf,
                  const float*  __restrict__ qf,
                  const float*  __restrict__ pos,
                  float* __restrict__ out) {
    const int tid = threadIdx.x;
    const int bid = blockIdx.x;

    // ================= paint (CTAs 0..63 only; cold path) ==============
    if (bid < PAINT_CTAS) {
        __shared__ float sx[NT], sy[NT];
        const int batch = bid >> 1;                    // 2 CTAs per batch
        const int row   = ((bid & 1) << 8) + tid;      // 0..511

        if (tid < NT * 2) {
            float v = pos[(batch * NT) * 2 + tid];
            if (tid & 1) sy[tid >> 1] = v; else sx[tid >> 1] = v;
        }
        __syncthreads();

        unsigned w[WORDS_PER_ROW];
        #pragma unroll
        for (int k = 0; k < WORDS_PER_ROW; k++) w[k] = 0u;

        for (int t = 0; t < NT; t++) {
            float x = sx[t], y = sy[t];
            if (!(x > 0.0f && y > 0.0f)) continue;
            int yp = (int)floorf(y * (float)NH);
            if (row < yp - BOX || row >= yp + BOX) continue;
            int xp = (int)floorf(x * (float)NW);
            int x0 = max(xp - BOX, 0);
            int x1 = min(xp + BOX, NW);
            if (x0 >= x1) continue;
            int w0 = x0 >> 5;
            int w1 = (x1 - 1) >> 5;
            if (w0 == w1) {
                w[w0] |= ((1u << (x1 - x0)) - 1u) << (x0 & 31);  // width<=10<32
            } else {
                w[w0] |= ~0u << (x0 & 31);
                w[w1] |= (1u << (x1 - (w1 << 5))) - 1u;          // 1..9 bits
            }
        }

        uint4* dst = (uint4*)&g_mask[batch * WORDS_PER_BATCH + row * WORDS_PER_ROW];
        #pragma unroll
        for (int k = 0; k < 4; k++)
            dst[k] = make_uint4(w[4 * k], w[4 * k + 1], w[4 * k + 2], w[4 * k + 3]);

        __syncthreads();
        if (tid == 0) {
            __threadfence();
            atomicAdd((unsigned*)&g_paint_done, 1u);
        }
    }

    // ================= Phase A: mask-free stream of sum(d^2) ===========
    float sum = 0.0f;
    {
        const int stride = RGRID * RTHREADS;
        #pragma unroll 4
        for (int i = bid * RTHREADS + tid; i < N4; i += stride) {
            float4 a = p4[i];
            float4 b = q4[i];
            float d0 = a.x - b.x;
            float d1 = a.y - b.y;
            float d2 = a.z - b.z;
            float d3 = a.w - b.w;
            sum = fmaf(d0, d0, sum);
            sum = fmaf(d1, d1, sum);
            sum = fmaf(d2, d2, sum);
            sum = fmaf(d3, d3, sum);
        }
    }

    // ======== wait for paint (all CTAs co-resident; stream >> paint) ====
    while (g_paint_done != PAINT_CTAS) { }
    __threadfence();

    // ================= Phase B: masked fixup, one word per thread ======
    {
        const int g = bid * RTHREADS + tid;
        if (g < MASK_WORDS) {
            unsigned w = g_mask[g];
            if (w) {
                const int batch = g >> 13;
                const int rem   = g & 8191;
                const int row   = rem >> 4;
                const int cbase = (rem & 15) << 5;
                // float index of (batch, ch=0, row, col=0)
                const int base = (batch << 20) + (row << 9);
                float bsum = 0.0f;
                while (w) {
                    int bit = __ffs(w) - 1;
                    w &= w - 1;
                    int idx = base + cbase + bit;
                    #pragma unroll
                    for (int ch = 0; ch < NC; ch++) {
                        float d = pf[idx + (ch << 18)] - qf[idx + (ch << 18)];
                        bsum = fmaf(d, d, bsum);
                    }
                }
                sum = fmaf(3.0f, bsum, sum);
            }
        }
    }

    // ================= block reduce + last-block fold ==================
    #pragma unroll
    for (int o = 16; o > 0; o >>= 1)
        sum += __shfl_xor_sync(0xFFFFFFFFu, sum, o);
    __shared__ float ssum[RTHREADS / 32];
    __shared__ bool  s_last;
    int lane = tid & 31, wid = tid >> 5;
    if (lane == 0) ssum[wid] = sum;
    __syncthreads();
    if (wid == 0) {
        float v = (lane < RTHREADS / 32) ? ssum[lane] : 0.0f;
        #pragma unroll
        for (int o = 4; o > 0; o >>= 1)
            v += __shfl_xor_sync(0xFFFFFFFFu, v, o);
        if (lane == 0) {
            g_partials[bid] = v;
            __threadfence();
            unsigned prev = atomicInc(&g_count, RGRID - 1);  // wraps after last
            s_last = (prev == RGRID - 1);
        }
    }
    __syncthreads();

    if (s_last) {
        double d = 0.0;
        for (int i = tid; i < RGRID; i += RTHREADS)
            d += (double)g_partials[i];
        #pragma unroll
        for (int o = 16; o > 0; o >>= 1)
            d += __shfl_xor_sync(0xFFFFFFFFu, d, o);
        __shared__ double dsum[RTHREADS / 32];
        if (lane == 0) dsum[wid] = d;
        __syncthreads();
        if (wid == 0) {
            double t = (lane < RTHREADS / 32) ? dsum[lane] : 0.0;
            #pragma unroll
            for (int o = 4; o > 0; o >>= 1)
                t += __shfl_xor_sync(0xFFFFFFFFu, t, o);
            if (lane == 0) {
                out[0] = (float)(t * (1.0 / (double)N_ELEMS));
                g_paint_done = 0;          // reset for next graph replay
                __threadfence();
            }
        }
    }
}

extern "C" void kernel_launch(void* const* d_in, const int* in_sizes, int n_in,
                              void* d_out, int out_size) {
    const float* pred = (const float*)d_in[0];
    const float* targ = (const float*)d_in[1];
    // d_in[2] (text_tokens) is unused by the math.
    const float* pos  = (const float*)d_in[3];
    fused_loss_kernel<<<RGRID, RTHREADS>>>((const float4*)pred,
                                           (const float4*)targ,
                                           pred, targ, pos, (float*)d_out);
}